// round 6
// baseline (speedup 1.0000x reference)
#include <cuda_runtime.h>
#include <cuda_fp16.h>
#include <cstdint>

#define IN_F   8192
#define OUT_F  8192
#define NTOK   32
#define NCODE  65536
#define GROUPS (IN_F / 8)   // 1024
#define KSPLIT 4
#define KSEG   (IN_F / KSPLIT)   // 2048
#define NIT    (KSEG / 64)       // 32
#define NCHUNK 8                 // 8192 = 8 x 1024
#define TILE_M 64

// ---------------- device scratch (no allocations allowed) ----------------
__device__ __align__(16) static __half g_cb16[NCODE * 8];        // 1 MB
__device__ __align__(16) static __half g_xh16[NTOK * IN_F];      // 512 KB
__device__ static float g_zpart[KSPLIT][NTOK * OUT_F];           // 4 MB
__device__ static float g_tmp[NTOK * IN_F];                      // 1 MB (FWHT mid)

// ---------------- helpers ----------------
__device__ __forceinline__ uint32_t smem_u32(const void* p) {
    uint32_t a;
    asm("{ .reg .u64 t; cvta.to.shared.u64 t, %1; cvt.u32.u64 %0, t; }"
        : "=r"(a) : "l"(p));
    return a;
}

#define SWZ(off) ((off) ^ (((off) >> 3) & 0x70))

__device__ __forceinline__ void ldmat_x4(uint32_t addr, uint32_t& r0, uint32_t& r1,
                                         uint32_t& r2, uint32_t& r3) {
    asm volatile("ldmatrix.sync.aligned.m8n8.x4.shared.b16 {%0,%1,%2,%3}, [%4];"
                 : "=r"(r0), "=r"(r1), "=r"(r2), "=r"(r3) : "r"(addr));
}
__device__ __forceinline__ void mma16816(float* c, uint32_t a0, uint32_t a1,
                                         uint32_t a2, uint32_t a3,
                                         uint32_t b0, uint32_t b1) {
    asm volatile("mma.sync.aligned.m16n8k16.row.col.f32.f16.f16.f32 "
                 "{%0,%1,%2,%3}, {%4,%5,%6,%7}, {%8,%9}, {%0,%1,%2,%3};"
                 : "+f"(c[0]), "+f"(c[1]), "+f"(c[2]), "+f"(c[3])
                 : "r"(a0), "r"(a1), "r"(a2), "r"(a3), "r"(b0), "r"(b1));
}

// In-smem FWHT over 1024 floats, 256 threads.
__device__ __forceinline__ void fwht1024(float* s, int tid) {
    for (int h = 1; h < 1024; h <<= 1) {
        __syncthreads();
        #pragma unroll
        for (int pp = 0; pp < 2; ++pp) {
            int p = tid + pp * 256;
            int i = 2 * p - (p & (h - 1));
            float a = s[i], b = s[i + h];
            s[i] = a + b;
            s[i + h] = a - b;
        }
    }
    __syncthreads();
}

// 8-point in-register FWHT
__device__ __forceinline__ void fwht8(float* v) {
    #pragma unroll
    for (int h = 1; h < 8; h <<= 1)
        #pragma unroll
        for (int c = 0; c < 8; ++c)
            if (!(c & h)) {
                float a = v[c], b = v[c + h];
                v[c] = a + b;
                v[c + h] = a - b;
            }
}

// ---------------- K_pre: fused codebook convert + FWHT stage 1 ----------------
__global__ void __launch_bounds__(256) k_pre(const float* __restrict__ cb,
                                             const float* __restrict__ x,
                                             const float* __restrict__ SU) {
    if (blockIdx.x < 256) {
        int r = blockIdx.x * 256 + threadIdx.x;
        const float4* p = reinterpret_cast<const float4*>(cb + (size_t)r * 8);
        float4 a = p[0], b = p[1];
        __half2 h0 = __floats2half2_rn(a.x, a.y);
        __half2 h1 = __floats2half2_rn(a.z, a.w);
        __half2 h2 = __floats2half2_rn(b.x, b.y);
        __half2 h3 = __floats2half2_rn(b.z, b.w);
        uint4 v;
        v.x = *reinterpret_cast<unsigned*>(&h0);
        v.y = *reinterpret_cast<unsigned*>(&h1);
        v.z = *reinterpret_cast<unsigned*>(&h2);
        v.w = *reinterpret_cast<unsigned*>(&h3);
        *reinterpret_cast<uint4*>(g_cb16 + (size_t)r * 8) = v;
        return;
    }
    __shared__ float s[1024];
    int bb = blockIdx.x - 256;        // 0..255
    int t = bb >> 3;                  // token
    int ch = bb & 7;                  // chunk
    size_t base = (size_t)t * IN_F + ch * 1024;
    int tid = threadIdx.x;
    #pragma unroll
    for (int pp = 0; pp < 4; ++pp) {
        int i = tid + pp * 256;
        s[i] = x[base + i] * SU[ch * 1024 + i];
    }
    fwht1024(s, tid);
    #pragma unroll
    for (int pp = 0; pp < 4; ++pp) {
        int i = tid + pp * 256;
        g_tmp[base + i] = s[i];
    }
}

// ---------------- K_xh2: FWHT stage 2 (H_8) -> fp16 xh ----------------
__global__ void __launch_bounds__(256) k_xh2() {
    int gid = blockIdx.x * 256 + threadIdx.x;   // 0..32767
    int t = gid >> 10;
    int i = gid & 1023;
    size_t base = (size_t)t * IN_F + i;
    float v[8];
    #pragma unroll
    for (int c = 0; c < 8; ++c) v[c] = g_tmp[base + c * 1024];
    fwht8(v);
    const float sc = 0.011048543456039806f;   // 1/sqrt(8192)
    #pragma unroll
    for (int c = 0; c < 8; ++c)
        g_xh16[base + c * 1024] = __float2half(v[c] * sc);
}

// ---------------- K2: gather-dequant + mma.sync ----------------
// grid (128, KSPLIT): x = output tile of 64 rows, y = K segment of 2048.
// Per iter: K-chunk 64. A tile 64x64 fp16 (8KB, SW128), B tile 32x64 fp16 (4KB).
// smem 24KB/CTA -> high occupancy. 8 warps = 4 m-chunks x 2 n-halves.
__global__ void __launch_bounds__(256) k_main(const int* __restrict__ Qidxs) {
    __shared__ __align__(128) unsigned char sm[24576]; // A0@0 A1@8192 B0@16384 B1@20480
    const uint32_t sb = smem_u32(sm);
    const int tid = threadIdx.x;
    const int wid = tid >> 5;
    const int lid = tid & 31;
    const int m0 = blockIdx.x * TILE_M;
    const int kbase = blockIdx.y * KSEG;

    const uint4* __restrict__ cbu = reinterpret_cast<const uint4*>(g_cb16);
    const __half* __restrict__ xh = g_xh16;

    const int r0 = tid >> 3;   // 0..31 (row slot & token)
    const int j  = tid & 7;    // 0..7  (16B column within 128B row)

    float c[2][4];
    #pragma unroll
    for (int g = 0; g < 2; ++g)
        #pragma unroll
        for (int i = 0; i < 4; ++i) c[g][i] = 0.0f;

    int q[2], qn[2];
    uint4 w[2];
    uint4 bv;

    const int* qrow = Qidxs + (size_t)(m0 + r0) * GROUPS + j;

    // prologue: gathers for it=0, indices for it=1
    {
        int g0 = (kbase) >> 3;
        q[0] = __ldg(qrow + g0);
        q[1] = __ldg(qrow + g0 + 32 * GROUPS);
        w[0] = __ldg(&cbu[q[0]]);
        w[1] = __ldg(&cbu[q[1]]);
        bv = *reinterpret_cast<const uint4*>(xh + (size_t)r0 * IN_F + kbase + j * 8);
        int g1 = (kbase + 64) >> 3;
        qn[0] = __ldg(qrow + g1);
        qn[1] = __ldg(qrow + g1 + 32 * GROUPS);
    }

    // ldmatrix address components
    const int a_row_in_tile = (lid & 7) + ((lid >> 3) & 1) * 8;     // 0..15
    const int a_kb_half     = ((lid >> 4) & 1) * 16;                // byte 0/16
    const int b_mat  = lid >> 3;                                    // 0..3
    const int b_nrow = ((b_mat >> 1) * 8) + (lid & 7);              // 0..15
    const int b_kb   = (b_mat & 1) * 16;                            // byte 0/16
    const int wm = wid & 3;          // m-chunk of 16
    const int nh = wid >> 2;         // n-half of 16 tokens
    const uint32_t b_base = ((uint32_t)(nh * 16 + b_nrow) << 7) + (uint32_t)b_kb;

    for (int it = 0; it < NIT; ++it) {
        const int s = it & 1;
        unsigned char* Ap = sm + s * 8192;
        unsigned char* Bp = sm + 16384 + s * 4096;

        // ---- store current tile ----
        {
            uint32_t boff = (uint32_t)((r0 << 7) | (j << 4));
            *reinterpret_cast<uint4*>(Bp + SWZ(boff)) = bv;
            uint32_t a0 = (uint32_t)(((r0 +  0) << 7) | (j << 4));
            uint32_t a1 = (uint32_t)(((r0 + 32) << 7) | (j << 4));
            *reinterpret_cast<uint4*>(Ap + SWZ(a0)) = w[0];
            *reinterpret_cast<uint4*>(Ap + SWZ(a1)) = w[1];
        }
        __syncthreads();

        // ---- prefetch next tile into registers ----
        const bool more = (it + 1 < NIT);
        uint4 wn0, wn1, bvn;
        if (more) {
            wn0 = __ldg(&cbu[qn[0]]);
            wn1 = __ldg(&cbu[qn[1]]);
            bvn = *reinterpret_cast<const uint4*>(
                xh + (size_t)r0 * IN_F + kbase + (it + 1) * 64 + j * 8);
        }
        int qn2[2];
        if (it + 2 < NIT) {
            int g2 = (kbase + (it + 2) * 64) >> 3;
            qn2[0] = __ldg(qrow + g2);
            qn2[1] = __ldg(qrow + g2 + 32 * GROUPS);
        }

        // ---- MMAs on buffer s ----
        const uint32_t Ab = sb + s * 8192;
        const uint32_t Bb = sb + 16384u + s * 4096;
        #pragma unroll
        for (int k16 = 0; k16 < 4; ++k16) {
            uint32_t a0r, a1r, a2r, a3r;
            {
                uint32_t off = (uint32_t)((wm * 16 + a_row_in_tile) << 7) +
                               (uint32_t)(k16 * 32 + a_kb_half);
                ldmat_x4(Ab + SWZ(off), a0r, a1r, a2r, a3r);
            }
            uint32_t b00, b01, b10, b11;
            {
                uint32_t off0 = b_base + (uint32_t)(k16 * 32);
                ldmat_x4(Bb + SWZ(off0), b00, b01, b10, b11);
            }
            mma16816(c[0], a0r, a1r, a2r, a3r, b00, b01);
            mma16816(c[1], a0r, a1r, a2r, a3r, b10, b11);
        }

        if (more) {
            w[0] = wn0; w[1] = wn1;
            bv = bvn;
            qn[0] = qn2[0]; qn[1] = qn2[1];
        }
    }

    // ---- epilogue ----
    // m16n8 f32 acc: c0,c1 -> row=lid>>2, cols (lid&3)*2,+1 ; c2,c3 -> row+8
    float* zp = g_zpart[blockIdx.y];
    const int row0 = m0 + wm * 16 + (lid >> 2);
    const int col0 = (lid & 3) * 2;
    #pragma unroll
    for (int g = 0; g < 2; ++g) {
        int t0 = nh * 16 + g * 8 + col0;
        zp[(size_t)(t0    ) * OUT_F + row0    ] = c[g][0];
        zp[(size_t)(t0 + 1) * OUT_F + row0    ] = c[g][1];
        zp[(size_t)(t0    ) * OUT_F + row0 + 8] = c[g][2];
        zp[(size_t)(t0 + 1) * OUT_F + row0 + 8] = c[g][3];
    }
}

// ---------------- K_out1: sum zparts + FWHT stage 1 (H_1024) ----------------
__global__ void __launch_bounds__(256) k_out1() {
    __shared__ float s[1024];
    int t = blockIdx.x >> 3;          // token
    int ch = blockIdx.x & 7;          // chunk
    size_t base = (size_t)t * OUT_F + ch * 1024;
    int tid = threadIdx.x;
    #pragma unroll
    for (int pp = 0; pp < 4; ++pp) {
        int i = tid + pp * 256;
        s[i] = (g_zpart[0][base + i] + g_zpart[1][base + i]) +
               (g_zpart[2][base + i] + g_zpart[3][base + i]);
    }
    fwht1024(s, tid);
    #pragma unroll
    for (int pp = 0; pp < 4; ++pp) {
        int i = tid + pp * 256;
        g_tmp[base + i] = s[i];
    }
}

// ---------------- K_out2: FWHT stage 2 (H_8) * SV * Wscale -> out ----------------
__global__ void __launch_bounds__(256) k_out2(const float* __restrict__ SV,
                                              const float* __restrict__ Wscale,
                                              float* __restrict__ out) {
    int gid = blockIdx.x * 256 + threadIdx.x;   // 0..32767
    int t = gid >> 10;
    int i = gid & 1023;
    size_t base = (size_t)t * OUT_F + i;
    float v[8];
    #pragma unroll
    for (int c = 0; c < 8; ++c) v[c] = g_tmp[base + c * 1024];
    fwht8(v);
    const float ws = Wscale[0] * 0.011048543456039806f;   // Wscale / sqrt(8192)
    #pragma unroll
    for (int c = 0; c < 8; ++c)
        out[base + c * 1024] = v[c] * ws * SV[i + c * 1024];
}

// ---------------- launch ----------------
extern "C" void kernel_launch(void* const* d_in, const int* in_sizes, int n_in,
                              void* d_out, int out_size) {
    const float* x      = (const float*)d_in[0];
    const float* cb     = (const float*)d_in[1];
    const int*   qidx   = (const int*)  d_in[2];
    const float* SU     = (const float*)d_in[3];
    const float* SV     = (const float*)d_in[4];
    const float* Wscale = (const float*)d_in[5];
    float* out = (float*)d_out;

    k_pre<<<512, 256>>>(cb, x, SU);
    k_xh2<<<NTOK * 1024 / 256, 256>>>();
    k_main<<<dim3(OUT_F / TILE_M, KSPLIT), 256>>>(qidx);
    k_out1<<<NTOK * NCHUNK, 256>>>();
    k_out2<<<NTOK * 1024 / 256, 256>>>(SV, Wscale, out);
}

// round 7
// speedup vs baseline: 1.1110x; 1.1110x over previous
#include <cuda_runtime.h>
#include <cuda_fp16.h>
#include <cstdint>

#define IN_F   8192
#define OUT_F  8192
#define NTOK   32
#define NCODE  65536
#define GROUPS (IN_F / 8)   // 1024
#define KSPLIT 8
#define KSEG   (IN_F / KSPLIT)   // 1024
#define NIT    (KSEG / 64)       // 16
#define NCHUNK 8                 // 8192 = 8 x 1024

// ---------------- device scratch (no allocations allowed) ----------------
__device__ __align__(16) static __half g_cb16[NCODE * 8];        // 1 MB
__device__ __align__(16) static __half g_xh16[NTOK * IN_F];      // 512 KB
__device__ static float g_zpart[KSPLIT][NTOK * OUT_F];           // 8 MB
__device__ static float g_tmp[NTOK * IN_F];                      // 1 MB (FWHT mid)

// ---------------- helpers ----------------
__device__ __forceinline__ uint32_t smem_u32(const void* p) {
    uint32_t a;
    asm("{ .reg .u64 t; cvta.to.shared.u64 t, %1; cvt.u32.u64 %0, t; }"
        : "=r"(a) : "l"(p));
    return a;
}

#define SWZ(off) ((off) ^ (((off) >> 3) & 0x70))

__device__ __forceinline__ void ldmat_x4(uint32_t addr, uint32_t& r0, uint32_t& r1,
                                         uint32_t& r2, uint32_t& r3) {
    asm volatile("ldmatrix.sync.aligned.m8n8.x4.shared.b16 {%0,%1,%2,%3}, [%4];"
                 : "=r"(r0), "=r"(r1), "=r"(r2), "=r"(r3) : "r"(addr));
}
__device__ __forceinline__ void mma16816(float* c, uint32_t a0, uint32_t a1,
                                         uint32_t a2, uint32_t a3,
                                         uint32_t b0, uint32_t b1) {
    asm volatile("mma.sync.aligned.m16n8k16.row.col.f32.f16.f16.f32 "
                 "{%0,%1,%2,%3}, {%4,%5,%6,%7}, {%8,%9}, {%0,%1,%2,%3};"
                 : "+f"(c[0]), "+f"(c[1]), "+f"(c[2]), "+f"(c[3])
                 : "r"(a0), "r"(a1), "r"(a2), "r"(a3), "r"(b0), "r"(b1));
}

// In-smem FWHT over 1024 floats, 256 threads.
__device__ __forceinline__ void fwht1024(float* s, int tid) {
    for (int h = 1; h < 1024; h <<= 1) {
        __syncthreads();
        #pragma unroll
        for (int pp = 0; pp < 2; ++pp) {
            int p = tid + pp * 256;
            int i = 2 * p - (p & (h - 1));
            float a = s[i], b = s[i + h];
            s[i] = a + b;
            s[i + h] = a - b;
        }
    }
    __syncthreads();
}

// 8-point in-register FWHT
__device__ __forceinline__ void fwht8(float* v) {
    #pragma unroll
    for (int h = 1; h < 8; h <<= 1)
        #pragma unroll
        for (int c = 0; c < 8; ++c)
            if (!(c & h)) {
                float a = v[c], b = v[c + h];
                v[c] = a + b;
                v[c + h] = a - b;
            }
}

// ---------------- K_pre: fused codebook convert + FWHT stage 1 ----------------
__global__ void __launch_bounds__(256) k_pre(const float* __restrict__ cb,
                                             const float* __restrict__ x,
                                             const float* __restrict__ SU) {
    if (blockIdx.x < 256) {
        int r = blockIdx.x * 256 + threadIdx.x;
        const float4* p = reinterpret_cast<const float4*>(cb + (size_t)r * 8);
        float4 a = p[0], b = p[1];
        __half2 h0 = __floats2half2_rn(a.x, a.y);
        __half2 h1 = __floats2half2_rn(a.z, a.w);
        __half2 h2 = __floats2half2_rn(b.x, b.y);
        __half2 h3 = __floats2half2_rn(b.z, b.w);
        uint4 v;
        v.x = *reinterpret_cast<unsigned*>(&h0);
        v.y = *reinterpret_cast<unsigned*>(&h1);
        v.z = *reinterpret_cast<unsigned*>(&h2);
        v.w = *reinterpret_cast<unsigned*>(&h3);
        *reinterpret_cast<uint4*>(g_cb16 + (size_t)r * 8) = v;
        return;
    }
    __shared__ float s[1024];
    int bb = blockIdx.x - 256;        // 0..255
    int t = bb >> 3;                  // token
    int ch = bb & 7;                  // chunk
    size_t base = (size_t)t * IN_F + ch * 1024;
    int tid = threadIdx.x;
    #pragma unroll
    for (int pp = 0; pp < 4; ++pp) {
        int i = tid + pp * 256;
        s[i] = x[base + i] * SU[ch * 1024 + i];
    }
    fwht1024(s, tid);
    #pragma unroll
    for (int pp = 0; pp < 4; ++pp) {
        int i = tid + pp * 256;
        g_tmp[base + i] = s[i];
    }
}

// ---------------- K_xh2: FWHT stage 2 (H_8) -> fp16 xh ----------------
__global__ void __launch_bounds__(256) k_xh2() {
    int gid = blockIdx.x * 256 + threadIdx.x;   // 0..32767
    int t = gid >> 10;
    int i = gid & 1023;
    size_t base = (size_t)t * IN_F + i;
    float v[8];
    #pragma unroll
    for (int c = 0; c < 8; ++c) v[c] = g_tmp[base + c * 1024];
    fwht8(v);
    const float sc = 0.011048543456039806f;   // 1/sqrt(8192)
    #pragma unroll
    for (int c = 0; c < 8; ++c)
        g_xh16[base + c * 1024] = __float2half(v[c] * sc);
}

// ---------------- K2: fragment-direct gather + mma.sync ----------------
// grid (64, 8): x = output tile of 128 rows, y = K segment of 1024.
// A fragments gathered straight from the codebook into registers (4B per lane
// per (k16, frag-reg)); quad shuffles broadcast the indices. Only B (xh tile,
// 4KB/iter) goes through smem (double-buffered, 1 sync/iter).
__global__ void __launch_bounds__(256, 2) k_main(const int* __restrict__ Qidxs) {
    __shared__ __align__(128) unsigned char sm[8192];   // B0@0, B1@4096
    const uint32_t sb = smem_u32(sm);
    const int tid = threadIdx.x;
    const int wid = tid >> 5;
    const int lid = tid & 31;
    const int q  = lid >> 2;      // quad 0..7  (fragment row within m16)
    const int cc = lid & 3;       // pair index 0..3
    const int m0 = blockIdx.x * 128;
    const int kbase = blockIdx.y * KSEG;
    const int gseg  = blockIdx.y * (KSEG / 8);   // group base (128 per seg)

    const __half* __restrict__ xh = g_xh16;
    const char*   __restrict__ cbb = reinterpret_cast<const char*>(g_cb16);

    // B store mapping (all 256 threads write the 32x64 B tile = 4KB)
    const int r0 = tid >> 3;   // token 0..31
    const int j  = tid & 7;    // 16B column

    // This lane's Qidxs int4 stream: row = m0 + wid*16 + q + 8*(cc&1),
    // groups [gseg + it*8 + 4*(cc>>1) .. +3]
    const int myrow = m0 + wid * 16 + q + 8 * (cc & 1);
    const int4* qp4 = reinterpret_cast<const int4*>(
        Qidxs + (size_t)myrow * GROUPS + gseg + 4 * (cc >> 1));
    // advance per iter: 8 groups = 2 int4

    float c[4][4];
    #pragma unroll
    for (int g = 0; g < 4; ++g)
        #pragma unroll
        for (int i = 0; i < 4; ++i) c[g][i] = 0.0f;

    // B ldmatrix constants
    const int b_mat  = lid >> 3;
    const int b_nrow = ((b_mat >> 1) * 8) + (lid & 7);
    const int b_kb   = (b_mat & 1) * 16;
    const uint32_t b_base = ((uint32_t)b_nrow << 7) + (uint32_t)b_kb;

    const uint32_t qmask = 0xffffffffu;
    const int qlane = lid & ~3;

// gather the 16 A-fragment regs for one iter from an idx int4
#define GATHER_FRAGS(AF, SIDX)                                                   \
    {                                                                            \
        int comps[4] = {(SIDX).x, (SIDX).y, (SIDX).z, (SIDX).w};                 \
        _Pragma("unroll")                                                        \
        for (int kk = 0; kk < 4; ++kk) {                                         \
            int hb = (kk >> 1) * 2;                                              \
            int i00 = __shfl_sync(qmask, comps[(2 * kk) & 3],     qlane + hb);   \
            int i10 = __shfl_sync(qmask, comps[(2 * kk) & 3],     qlane + hb + 1);\
            int i01 = __shfl_sync(qmask, comps[(2 * kk + 1) & 3], qlane + hb);   \
            int i11 = __shfl_sync(qmask, comps[(2 * kk + 1) & 3], qlane + hb + 1);\
            (AF)[4 * kk + 0] = *reinterpret_cast<const uint32_t*>(               \
                cbb + (size_t)i00 * 16 + cc * 4);                                \
            (AF)[4 * kk + 1] = *reinterpret_cast<const uint32_t*>(               \
                cbb + (size_t)i10 * 16 + cc * 4);                                \
            (AF)[4 * kk + 2] = *reinterpret_cast<const uint32_t*>(               \
                cbb + (size_t)i01 * 16 + cc * 4);                                \
            (AF)[4 * kk + 3] = *reinterpret_cast<const uint32_t*>(               \
                cbb + (size_t)i11 * 16 + cc * 4);                                \
        }                                                                        \
    }

    // ---- prologue ----
    int4 sidx0 = __ldg(qp4);          // idx for it=0
    int4 sidx1 = __ldg(qp4 + 2);      // idx for it=1
    uint4 bv = *reinterpret_cast<const uint4*>(xh + (size_t)r0 * IN_F + kbase + j * 8);

    uint32_t af[16];
    GATHER_FRAGS(af, sidx0);

    for (int it = 0; it < NIT; ++it) {
        const int s = it & 1;

        // store this iter's B tile
        uint32_t boff = (uint32_t)((r0 << 7) | (j << 4));
        *reinterpret_cast<uint4*>(sm + s * 4096 + SWZ(boff)) = bv;
        __syncthreads();

        // ---- prefetch next iter (A frags + B + idx), latency hidden by MMAs ----
        const bool more = (it + 1 < NIT);
        uint32_t afN[16];
        int4 sidxN;
        uint4 bvn;
        if (more) {
            bvn = *reinterpret_cast<const uint4*>(
                xh + (size_t)r0 * IN_F + kbase + (it + 1) * 64 + j * 8);
            GATHER_FRAGS(afN, sidx1);
            if (it + 2 < NIT) sidxN = __ldg(qp4 + (it + 2) * 2);
        }

        // ---- MMAs on buffer s ----
        const uint32_t Bb = sb + (uint32_t)s * 4096;
        #pragma unroll
        for (int kk = 0; kk < 4; ++kk) {
            uint32_t b00, b01, b10, b11, b20, b21, b30, b31;
            uint32_t off0 = b_base + (uint32_t)(kk * 32);
            ldmat_x4(Bb + SWZ(off0), b00, b01, b10, b11);
            uint32_t off1 = off0 + (16u << 7);   // tokens +16
            ldmat_x4(Bb + SWZ(off1), b20, b21, b30, b31);
            mma16816(c[0], af[4*kk], af[4*kk+1], af[4*kk+2], af[4*kk+3], b00, b01);
            mma16816(c[1], af[4*kk], af[4*kk+1], af[4*kk+2], af[4*kk+3], b10, b11);
            mma16816(c[2], af[4*kk], af[4*kk+1], af[4*kk+2], af[4*kk+3], b20, b21);
            mma16816(c[3], af[4*kk], af[4*kk+1], af[4*kk+2], af[4*kk+3], b30, b31);
        }

        if (more) {
            #pragma unroll
            for (int i = 0; i < 16; ++i) af[i] = afN[i];
            sidx1 = sidxN;
            bv = bvn;
        }
    }
#undef GATHER_FRAGS

    // ---- epilogue: scatter accumulators to z partials ----
    float* zp = g_zpart[blockIdx.y];
    const int row0 = m0 + wid * 16 + (lid >> 2);
    const int col0 = (lid & 3) * 2;
    #pragma unroll
    for (int g = 0; g < 4; ++g) {
        int t0 = g * 8 + col0;
        zp[(size_t)(t0    ) * OUT_F + row0    ] = c[g][0];
        zp[(size_t)(t0 + 1) * OUT_F + row0    ] = c[g][1];
        zp[(size_t)(t0    ) * OUT_F + row0 + 8] = c[g][2];
        zp[(size_t)(t0 + 1) * OUT_F + row0 + 8] = c[g][3];
    }
}

// ---------------- K_out1: sum zparts + FWHT stage 1 (H_1024) ----------------
__global__ void __launch_bounds__(256) k_out1() {
    __shared__ float s[1024];
    int t = blockIdx.x >> 3;          // token
    int ch = blockIdx.x & 7;          // chunk
    size_t base = (size_t)t * OUT_F + ch * 1024;
    int tid = threadIdx.x;
    #pragma unroll
    for (int pp = 0; pp < 4; ++pp) {
        int i = tid + pp * 256;
        float acc = 0.0f;
        #pragma unroll
        for (int p = 0; p < KSPLIT; ++p) acc += g_zpart[p][base + i];
        s[i] = acc;
    }
    fwht1024(s, tid);
    #pragma unroll
    for (int pp = 0; pp < 4; ++pp) {
        int i = tid + pp * 256;
        g_tmp[base + i] = s[i];
    }
}

// ---------------- K_out2: FWHT stage 2 (H_8) * SV * Wscale -> out ----------------
__global__ void __launch_bounds__(256) k_out2(const float* __restrict__ SV,
                                              const float* __restrict__ Wscale,
                                              float* __restrict__ out) {
    int gid = blockIdx.x * 256 + threadIdx.x;   // 0..32767
    int t = gid >> 10;
    int i = gid & 1023;
    size_t base = (size_t)t * OUT_F + i;
    float v[8];
    #pragma unroll
    for (int c = 0; c < 8; ++c) v[c] = g_tmp[base + c * 1024];
    fwht8(v);
    const float ws = Wscale[0] * 0.011048543456039806f;   // Wscale / sqrt(8192)
    #pragma unroll
    for (int c = 0; c < 8; ++c)
        out[base + c * 1024] = v[c] * ws * SV[i + c * 1024];
}

// ---------------- launch ----------------
extern "C" void kernel_launch(void* const* d_in, const int* in_sizes, int n_in,
                              void* d_out, int out_size) {
    const float* x      = (const float*)d_in[0];
    const float* cb     = (const float*)d_in[1];
    const int*   qidx   = (const int*)  d_in[2];
    const float* SU     = (const float*)d_in[3];
    const float* SV     = (const float*)d_in[4];
    const float* Wscale = (const float*)d_in[5];
    float* out = (float*)d_out;

    k_pre<<<512, 256>>>(cb, x, SU);
    k_xh2<<<NTOK * 1024 / 256, 256>>>();
    k_main<<<dim3(OUT_F / 128, KSPLIT), 256>>>(qidx);
    k_out1<<<NTOK * NCHUNK, 256>>>();
    k_out2<<<NTOK * 1024 / 256, 256>>>(SV, Wscale, out);
}

// round 8
// speedup vs baseline: 1.1859x; 1.0675x over previous
#include <cuda_runtime.h>
#include <cuda_fp16.h>
#include <cstdint>

#define IN_F   8192
#define OUT_F  8192
#define NTOK   32
#define NCODE  65536
#define GROUPS (IN_F / 8)   // 1024
#define KSPLIT 16
#define KSEG   (IN_F / KSPLIT)   // 512
#define NIT    (KSEG / 64)       // 8
#define NCHUNK 8                 // 8192 = 8 x 1024

// ---------------- device scratch (no allocations allowed) ----------------
__device__ __align__(16) static __half g_cb16[NCODE * 8];        // 1 MB
__device__ __align__(16) static __half g_xh16[NTOK * IN_F];      // 512 KB
__device__ __align__(16) static float g_zpart[KSPLIT][NTOK * OUT_F];  // 16 MB
__device__ __align__(16) static float g_tmp[NTOK * IN_F];        // 1 MB (FWHT mid)

// ---------------- helpers ----------------
__device__ __forceinline__ uint32_t smem_u32(const void* p) {
    uint32_t a;
    asm("{ .reg .u64 t; cvta.to.shared.u64 t, %1; cvt.u32.u64 %0, t; }"
        : "=r"(a) : "l"(p));
    return a;
}

#define SWZ(off) ((off) ^ (((off) >> 3) & 0x70))

__device__ __forceinline__ void ldmat_x4(uint32_t addr, uint32_t& r0, uint32_t& r1,
                                         uint32_t& r2, uint32_t& r3) {
    asm volatile("ldmatrix.sync.aligned.m8n8.x4.shared.b16 {%0,%1,%2,%3}, [%4];"
                 : "=r"(r0), "=r"(r1), "=r"(r2), "=r"(r3) : "r"(addr));
}
__device__ __forceinline__ void mma16816(float* c, uint32_t a0, uint32_t a1,
                                         uint32_t a2, uint32_t a3,
                                         uint32_t b0, uint32_t b1) {
    asm volatile("mma.sync.aligned.m16n8k16.row.col.f32.f16.f16.f32 "
                 "{%0,%1,%2,%3}, {%4,%5,%6,%7}, {%8,%9}, {%0,%1,%2,%3};"
                 : "+f"(c[0]), "+f"(c[1]), "+f"(c[2]), "+f"(c[3])
                 : "r"(a0), "r"(a1), "r"(a2), "r"(a3), "r"(b0), "r"(b1));
}

// In-smem FWHT over 1024 floats, 256 threads.
__device__ __forceinline__ void fwht1024(float* s, int tid) {
    for (int h = 1; h < 1024; h <<= 1) {
        __syncthreads();
        #pragma unroll
        for (int pp = 0; pp < 2; ++pp) {
            int p = tid + pp * 256;
            int i = 2 * p - (p & (h - 1));
            float a = s[i], b = s[i + h];
            s[i] = a + b;
            s[i + h] = a - b;
        }
    }
    __syncthreads();
}

// 8-point in-register FWHT
__device__ __forceinline__ void fwht8(float* v) {
    #pragma unroll
    for (int h = 1; h < 8; h <<= 1)
        #pragma unroll
        for (int c = 0; c < 8; ++c)
            if (!(c & h)) {
                float a = v[c], b = v[c + h];
                v[c] = a + b;
                v[c + h] = a - b;
            }
}

// ---------------- K_pre: fused codebook convert + FWHT stage 1 ----------------
__global__ void __launch_bounds__(256) k_pre(const float* __restrict__ cb,
                                             const float* __restrict__ x,
                                             const float* __restrict__ SU) {
    if (blockIdx.x < 256) {
        int r = blockIdx.x * 256 + threadIdx.x;
        const float4* p = reinterpret_cast<const float4*>(cb + (size_t)r * 8);
        float4 a = p[0], b = p[1];
        __half2 h0 = __floats2half2_rn(a.x, a.y);
        __half2 h1 = __floats2half2_rn(a.z, a.w);
        __half2 h2 = __floats2half2_rn(b.x, b.y);
        __half2 h3 = __floats2half2_rn(b.z, b.w);
        uint4 v;
        v.x = *reinterpret_cast<unsigned*>(&h0);
        v.y = *reinterpret_cast<unsigned*>(&h1);
        v.z = *reinterpret_cast<unsigned*>(&h2);
        v.w = *reinterpret_cast<unsigned*>(&h3);
        *reinterpret_cast<uint4*>(g_cb16 + (size_t)r * 8) = v;
        return;
    }
    __shared__ float s[1024];
    int bb = blockIdx.x - 256;        // 0..255
    int t = bb >> 3;                  // token
    int ch = bb & 7;                  // chunk
    size_t base = (size_t)t * IN_F + ch * 1024;
    int tid = threadIdx.x;
    {
        float4 xv = reinterpret_cast<const float4*>(x + base)[tid];
        float4 sv = reinterpret_cast<const float4*>(SU + ch * 1024)[tid];
        float4 r;
        r.x = xv.x * sv.x; r.y = xv.y * sv.y;
        r.z = xv.z * sv.z; r.w = xv.w * sv.w;
        reinterpret_cast<float4*>(s)[tid] = r;
    }
    fwht1024(s, tid);
    #pragma unroll
    for (int pp = 0; pp < 4; ++pp) {
        int i = tid + pp * 256;
        g_tmp[base + i] = s[i];
    }
}

// ---------------- K_xh2: FWHT stage 2 (H_8) -> fp16 xh ----------------
__global__ void __launch_bounds__(256) k_xh2() {
    int gid = blockIdx.x * 256 + threadIdx.x;   // 0..32767
    int t = gid >> 10;
    int i = gid & 1023;
    size_t base = (size_t)t * IN_F + i;
    float v[8];
    #pragma unroll
    for (int c = 0; c < 8; ++c) v[c] = g_tmp[base + c * 1024];
    fwht8(v);
    const float sc = 0.011048543456039806f;   // 1/sqrt(8192)
    #pragma unroll
    for (int c = 0; c < 8; ++c)
        g_xh16[base + c * 1024] = __float2half(v[c] * sc);
}

// ---------------- K2: fragment-direct gather + mma.sync ----------------
// grid (64, 16): x = output tile of 128 rows, y = K segment of 512.
// A fragments gathered straight from the codebook into registers (4B per lane
// per (k16, frag-reg)); quad shuffles broadcast the indices. Only B (xh tile,
// 4KB/iter) goes through smem (double-buffered, 1 sync/iter).
__global__ void __launch_bounds__(256, 2) k_main(const int* __restrict__ Qidxs) {
    __shared__ __align__(128) unsigned char sm[8192];   // B0@0, B1@4096
    const uint32_t sb = smem_u32(sm);
    const int tid = threadIdx.x;
    const int wid = tid >> 5;
    const int lid = tid & 31;
    const int q  = lid >> 2;      // quad 0..7  (fragment row within m16)
    const int cc = lid & 3;       // pair index 0..3
    const int m0 = blockIdx.x * 128;
    const int kbase = blockIdx.y * KSEG;
    const int gseg  = blockIdx.y * (KSEG / 8);   // group base (64 per seg)

    const __half* __restrict__ xh = g_xh16;
    const char*   __restrict__ cbb = reinterpret_cast<const char*>(g_cb16);

    // B store mapping (all 256 threads write the 32x64 B tile = 4KB)
    const int r0 = tid >> 3;   // token 0..31
    const int j  = tid & 7;    // 16B column

    // This lane's Qidxs int4 stream: row = m0 + wid*16 + q + 8*(cc&1),
    // groups [gseg + it*8 + 4*(cc>>1) .. +3]
    const int myrow = m0 + wid * 16 + q + 8 * (cc & 1);
    const int4* qp4 = reinterpret_cast<const int4*>(
        Qidxs + (size_t)myrow * GROUPS + gseg + 4 * (cc >> 1));
    // advance per iter: 8 groups = 2 int4

    float c[4][4];
    #pragma unroll
    for (int g = 0; g < 4; ++g)
        #pragma unroll
        for (int i = 0; i < 4; ++i) c[g][i] = 0.0f;

    // B ldmatrix constants
    const int b_mat  = lid >> 3;
    const int b_nrow = ((b_mat >> 1) * 8) + (lid & 7);
    const int b_kb   = (b_mat & 1) * 16;
    const uint32_t b_base = ((uint32_t)b_nrow << 7) + (uint32_t)b_kb;

    const uint32_t qmask = 0xffffffffu;
    const int qlane = lid & ~3;

// gather the 16 A-fragment regs for one iter from an idx int4
#define GATHER_FRAGS(AF, SIDX)                                                   \
    {                                                                            \
        int comps[4] = {(SIDX).x, (SIDX).y, (SIDX).z, (SIDX).w};                 \
        _Pragma("unroll")                                                        \
        for (int kk = 0; kk < 4; ++kk) {                                         \
            int hb = (kk >> 1) * 2;                                              \
            int i00 = __shfl_sync(qmask, comps[(2 * kk) & 3],     qlane + hb);   \
            int i10 = __shfl_sync(qmask, comps[(2 * kk) & 3],     qlane + hb + 1);\
            int i01 = __shfl_sync(qmask, comps[(2 * kk + 1) & 3], qlane + hb);   \
            int i11 = __shfl_sync(qmask, comps[(2 * kk + 1) & 3], qlane + hb + 1);\
            (AF)[4 * kk + 0] = *reinterpret_cast<const uint32_t*>(               \
                cbb + (size_t)i00 * 16 + cc * 4);                                \
            (AF)[4 * kk + 1] = *reinterpret_cast<const uint32_t*>(               \
                cbb + (size_t)i10 * 16 + cc * 4);                                \
            (AF)[4 * kk + 2] = *reinterpret_cast<const uint32_t*>(               \
                cbb + (size_t)i01 * 16 + cc * 4);                                \
            (AF)[4 * kk + 3] = *reinterpret_cast<const uint32_t*>(               \
                cbb + (size_t)i11 * 16 + cc * 4);                                \
        }                                                                        \
    }

    // ---- prologue ----
    int4 sidx0 = __ldg(qp4);          // idx for it=0
    int4 sidx1 = __ldg(qp4 + 2);      // idx for it=1
    uint4 bv = *reinterpret_cast<const uint4*>(xh + (size_t)r0 * IN_F + kbase + j * 8);

    uint32_t af[16];
    GATHER_FRAGS(af, sidx0);

    for (int it = 0; it < NIT; ++it) {
        const int s = it & 1;

        // store this iter's B tile
        uint32_t boff = (uint32_t)((r0 << 7) | (j << 4));
        *reinterpret_cast<uint4*>(sm + s * 4096 + SWZ(boff)) = bv;
        __syncthreads();

        // ---- prefetch next iter (A frags + B + idx), latency hidden by MMAs ----
        const bool more = (it + 1 < NIT);
        uint32_t afN[16];
        int4 sidxN;
        uint4 bvn;
        if (more) {
            bvn = *reinterpret_cast<const uint4*>(
                xh + (size_t)r0 * IN_F + kbase + (it + 1) * 64 + j * 8);
            GATHER_FRAGS(afN, sidx1);
            if (it + 2 < NIT) sidxN = __ldg(qp4 + (it + 2) * 2);
        }

        // ---- MMAs on buffer s ----
        const uint32_t Bb = sb + (uint32_t)s * 4096;
        #pragma unroll
        for (int kk = 0; kk < 4; ++kk) {
            uint32_t b00, b01, b10, b11, b20, b21, b30, b31;
            uint32_t off0 = b_base + (uint32_t)(kk * 32);
            ldmat_x4(Bb + SWZ(off0), b00, b01, b10, b11);
            uint32_t off1 = off0 + (16u << 7);   // tokens +16
            ldmat_x4(Bb + SWZ(off1), b20, b21, b30, b31);
            mma16816(c[0], af[4*kk], af[4*kk+1], af[4*kk+2], af[4*kk+3], b00, b01);
            mma16816(c[1], af[4*kk], af[4*kk+1], af[4*kk+2], af[4*kk+3], b10, b11);
            mma16816(c[2], af[4*kk], af[4*kk+1], af[4*kk+2], af[4*kk+3], b20, b21);
            mma16816(c[3], af[4*kk], af[4*kk+1], af[4*kk+2], af[4*kk+3], b30, b31);
        }

        if (more) {
            #pragma unroll
            for (int i = 0; i < 16; ++i) af[i] = afN[i];
            sidx1 = sidxN;
            bv = bvn;
        }
    }
#undef GATHER_FRAGS

    // ---- epilogue: scatter accumulators to z partials ----
    float* zp = g_zpart[blockIdx.y];
    const int row0 = m0 + wid * 16 + (lid >> 2);
    const int col0 = (lid & 3) * 2;
    #pragma unroll
    for (int g = 0; g < 4; ++g) {
        int t0 = g * 8 + col0;
        zp[(size_t)(t0    ) * OUT_F + row0    ] = c[g][0];
        zp[(size_t)(t0 + 1) * OUT_F + row0    ] = c[g][1];
        zp[(size_t)(t0    ) * OUT_F + row0 + 8] = c[g][2];
        zp[(size_t)(t0 + 1) * OUT_F + row0 + 8] = c[g][3];
    }
}

// ---------------- K_out1: sum zparts + FWHT stage 1 (H_1024) ----------------
__global__ void __launch_bounds__(256) k_out1() {
    __shared__ float s[1024];
    int t = blockIdx.x >> 3;          // token
    int ch = blockIdx.x & 7;          // chunk
    size_t base = (size_t)t * OUT_F + ch * 1024;
    int tid = threadIdx.x;
    {
        float4 acc = make_float4(0.f, 0.f, 0.f, 0.f);
        #pragma unroll
        for (int p = 0; p < KSPLIT; ++p) {
            float4 v = reinterpret_cast<const float4*>(g_zpart[p] + base)[tid];
            acc.x += v.x; acc.y += v.y; acc.z += v.z; acc.w += v.w;
        }
        reinterpret_cast<float4*>(s)[tid] = acc;
    }
    fwht1024(s, tid);
    #pragma unroll
    for (int pp = 0; pp < 4; ++pp) {
        int i = tid + pp * 256;
        g_tmp[base + i] = s[i];
    }
}

// ---------------- K_out2: FWHT stage 2 (H_8) * SV * Wscale -> out ----------------
__global__ void __launch_bounds__(256) k_out2(const float* __restrict__ SV,
                                              const float* __restrict__ Wscale,
                                              float* __restrict__ out) {
    int gid = blockIdx.x * 256 + threadIdx.x;   // 0..32767
    int t = gid >> 10;
    int i = gid & 1023;
    size_t base = (size_t)t * OUT_F + i;
    float v[8];
    #pragma unroll
    for (int c = 0; c < 8; ++c) v[c] = g_tmp[base + c * 1024];
    fwht8(v);
    const float ws = Wscale[0] * 0.011048543456039806f;   // Wscale / sqrt(8192)
    #pragma unroll
    for (int c = 0; c < 8; ++c)
        out[base + c * 1024] = v[c] * ws * SV[i + c * 1024];
}

// ---------------- launch ----------------
extern "C" void kernel_launch(void* const* d_in, const int* in_sizes, int n_in,
                              void* d_out, int out_size) {
    const float* x      = (const float*)d_in[0];
    const float* cb     = (const float*)d_in[1];
    const int*   qidx   = (const int*)  d_in[2];
    const float* SU     = (const float*)d_in[3];
    const float* SV     = (const float*)d_in[4];
    const float* Wscale = (const float*)d_in[5];
    float* out = (float*)d_out;

    k_pre<<<512, 256>>>(cb, x, SU);
    k_xh2<<<NTOK * 1024 / 256, 256>>>();
    k_main<<<dim3(OUT_F / 128, KSPLIT), 256>>>(qidx);
    k_out1<<<NTOK * NCHUNK, 256>>>();
    k_out2<<<NTOK * 1024 / 256, 256>>>(SV, Wscale, out);
}

// round 11
// speedup vs baseline: 1.2251x; 1.0330x over previous
#include <cuda_runtime.h>
#include <cuda_fp16.h>
#include <cstdint>

#define IN_F   8192
#define OUT_F  8192
#define NTOK   32
#define NCODE  65536
#define GROUPS (IN_F / 8)   // 1024
#define KSPLIT 16
#define KSEG   (IN_F / KSPLIT)   // 512
#define NIT    (KSEG / 64)       // 8
#define NCHUNK 8                 // 8192 = 8 x 1024

// ---------------- device scratch (no allocations allowed) ----------------
__device__ __align__(16) static __half g_cb16[NCODE * 8];        // 1 MB
__device__ __align__(16) static __half g_xh16[NTOK * IN_F];      // 512 KB
__device__ __align__(16) static float g_z[NTOK * OUT_F];         // 1 MB (atomic accum)
__device__ __align__(16) static float g_tmp[NTOK * IN_F];        // 1 MB (FWHT mid)

// ---------------- helpers ----------------
__device__ __forceinline__ uint32_t smem_u32(const void* p) {
    uint32_t a;
    asm("{ .reg .u64 t; cvta.to.shared.u64 t, %1; cvt.u32.u64 %0, t; }"
        : "=r"(a) : "l"(p));
    return a;
}

#define SWZ(off) ((off) ^ (((off) >> 3) & 0x70))

__device__ __forceinline__ void ldmat_x4(uint32_t addr, uint32_t& r0, uint32_t& r1,
                                         uint32_t& r2, uint32_t& r3) {
    asm volatile("ldmatrix.sync.aligned.m8n8.x4.shared.b16 {%0,%1,%2,%3}, [%4];"
                 : "=r"(r0), "=r"(r1), "=r"(r2), "=r"(r3) : "r"(addr));
}
__device__ __forceinline__ void mma16816(float* c, uint32_t a0, uint32_t a1,
                                         uint32_t a2, uint32_t a3,
                                         uint32_t b0, uint32_t b1) {
    asm volatile("mma.sync.aligned.m16n8k16.row.col.f32.f16.f16.f32 "
                 "{%0,%1,%2,%3}, {%4,%5,%6,%7}, {%8,%9}, {%0,%1,%2,%3};"
                 : "+f"(c[0]), "+f"(c[1]), "+f"(c[2]), "+f"(c[3])
                 : "r"(a0), "r"(a1), "r"(a2), "r"(a3), "r"(b0), "r"(b1));
}

// In-smem FWHT over 1024 floats, 256 threads.
__device__ __forceinline__ void fwht1024(float* s, int tid) {
    for (int h = 1; h < 1024; h <<= 1) {
        __syncthreads();
        #pragma unroll
        for (int pp = 0; pp < 2; ++pp) {
            int p = tid + pp * 256;
            int i = 2 * p - (p & (h - 1));
            float a = s[i], b = s[i + h];
            s[i] = a + b;
            s[i + h] = a - b;
        }
    }
    __syncthreads();
}

// 8-point in-register FWHT
__device__ __forceinline__ void fwht8(float* v) {
    #pragma unroll
    for (int h = 1; h < 8; h <<= 1)
        #pragma unroll
        for (int c = 0; c < 8; ++c)
            if (!(c & h)) {
                float a = v[c], b = v[c + h];
                v[c] = a + b;
                v[c + h] = a - b;
            }
}

// ---------------- K_pre: codebook convert + FWHT stage 1 + zero g_z ----------------
// blocks [0,256): codebook fp32->fp16; [256,512): H_1024 of x*SU; [512,576): zero g_z
__global__ void __launch_bounds__(256) k_pre(const float* __restrict__ cb,
                                             const float* __restrict__ x,
                                             const float* __restrict__ SU) {
    if (blockIdx.x >= 512) {
        // zero g_z: 65536 float4 total; 64 blocks x 1024 float4 each, contiguous
        int b4 = (blockIdx.x - 512) * 1024;
        float4 zz = make_float4(0.f, 0.f, 0.f, 0.f);
        #pragma unroll
        for (int pp = 0; pp < 4; ++pp)
            reinterpret_cast<float4*>(g_z)[(size_t)b4 + pp * 256 + threadIdx.x] = zz;
        return;
    }
    if (blockIdx.x < 256) {
        int r = blockIdx.x * 256 + threadIdx.x;
        const float4* p = reinterpret_cast<const float4*>(cb + (size_t)r * 8);
        float4 a = p[0], b = p[1];
        __half2 h0 = __floats2half2_rn(a.x, a.y);
        __half2 h1 = __floats2half2_rn(a.z, a.w);
        __half2 h2 = __floats2half2_rn(b.x, b.y);
        __half2 h3 = __floats2half2_rn(b.z, b.w);
        uint4 v;
        v.x = *reinterpret_cast<unsigned*>(&h0);
        v.y = *reinterpret_cast<unsigned*>(&h1);
        v.z = *reinterpret_cast<unsigned*>(&h2);
        v.w = *reinterpret_cast<unsigned*>(&h3);
        *reinterpret_cast<uint4*>(g_cb16 + (size_t)r * 8) = v;
        return;
    }
    __shared__ float s[1024];
    int bb = blockIdx.x - 256;        // 0..255
    int t = bb >> 3;                  // token
    int ch = bb & 7;                  // chunk
    size_t base = (size_t)t * IN_F + ch * 1024;
    int tid = threadIdx.x;
    {
        float4 xv = reinterpret_cast<const float4*>(x + base)[tid];
        float4 sv = reinterpret_cast<const float4*>(SU + ch * 1024)[tid];
        float4 r;
        r.x = xv.x * sv.x; r.y = xv.y * sv.y;
        r.z = xv.z * sv.z; r.w = xv.w * sv.w;
        reinterpret_cast<float4*>(s)[tid] = r;
    }
    fwht1024(s, tid);
    #pragma unroll
    for (int pp = 0; pp < 4; ++pp) {
        int i = tid + pp * 256;
        g_tmp[base + i] = s[i];
    }
}

// ---------------- K_xh2: FWHT stage 2 (H_8) -> fp16 xh ----------------
__global__ void __launch_bounds__(256) k_xh2() {
    int gid = blockIdx.x * 256 + threadIdx.x;   // 0..32767
    int t = gid >> 10;
    int i = gid & 1023;
    size_t base = (size_t)t * IN_F + i;
    float v[8];
    #pragma unroll
    for (int c = 0; c < 8; ++c) v[c] = g_tmp[base + c * 1024];
    fwht8(v);
    const float sc = 0.011048543456039806f;   // 1/sqrt(8192)
    #pragma unroll
    for (int c = 0; c < 8; ++c)
        g_xh16[base + c * 1024] = __float2half(v[c] * sc);
}

// ---------------- K2: fragment-direct gather + mma.sync ----------------
// grid (64, 16): x = output tile of 128 rows, y = K segment of 512.
// A fragments gathered straight from the codebook into registers (4B per lane
// per (k16, frag-reg)); quad shuffles broadcast the indices. Only B (xh tile,
// 4KB/iter) goes through smem (double-buffered, 1 sync/iter).
// Epilogue: REDG atomic accumulation into the single g_z buffer.
__global__ void __launch_bounds__(256, 2) k_main(const int* __restrict__ Qidxs) {
    __shared__ __align__(128) unsigned char sm[8192];   // B0@0, B1@4096
    const uint32_t sb = smem_u32(sm);
    const int tid = threadIdx.x;
    const int wid = tid >> 5;
    const int lid = tid & 31;
    const int q  = lid >> 2;      // quad 0..7  (fragment row within m16)
    const int cc = lid & 3;       // pair index 0..3
    const int m0 = blockIdx.x * 128;
    const int kbase = blockIdx.y * KSEG;
    const int gseg  = blockIdx.y * (KSEG / 8);   // group base (64 per seg)

    const __half* __restrict__ xh = g_xh16;
    const char*   __restrict__ cbb = reinterpret_cast<const char*>(g_cb16);

    // B store mapping (all 256 threads write the 32x64 B tile = 4KB)
    const int r0 = tid >> 3;   // token 0..31
    const int j  = tid & 7;    // 16B column

    // This lane's Qidxs int4 stream: row = m0 + wid*16 + q + 8*(cc&1),
    // groups [gseg + it*8 + 4*(cc>>1) .. +3]
    const int myrow = m0 + wid * 16 + q + 8 * (cc & 1);
    const int4* qp4 = reinterpret_cast<const int4*>(
        Qidxs + (size_t)myrow * GROUPS + gseg + 4 * (cc >> 1));
    // advance per iter: 8 groups = 2 int4

    float c[4][4];
    #pragma unroll
    for (int g = 0; g < 4; ++g)
        #pragma unroll
        for (int i = 0; i < 4; ++i) c[g][i] = 0.0f;

    // B ldmatrix constants
    const int b_mat  = lid >> 3;
    const int b_nrow = ((b_mat >> 1) * 8) + (lid & 7);
    const int b_kb   = (b_mat & 1) * 16;
    const uint32_t b_base = ((uint32_t)b_nrow << 7) + (uint32_t)b_kb;

    const uint32_t qmask = 0xffffffffu;
    const int qlane = lid & ~3;

// gather the 16 A-fragment regs for one iter from an idx int4
#define GATHER_FRAGS(AF, SIDX)                                                   \
    {                                                                            \
        int comps[4] = {(SIDX).x, (SIDX).y, (SIDX).z, (SIDX).w};                 \
        _Pragma("unroll")                                                        \
        for (int kk = 0; kk < 4; ++kk) {                                         \
            int hb = (kk >> 1) * 2;                                              \
            int i00 = __shfl_sync(qmask, comps[(2 * kk) & 3],     qlane + hb);   \
            int i10 = __shfl_sync(qmask, comps[(2 * kk) & 3],     qlane + hb + 1);\
            int i01 = __shfl_sync(qmask, comps[(2 * kk + 1) & 3], qlane + hb);   \
            int i11 = __shfl_sync(qmask, comps[(2 * kk + 1) & 3], qlane + hb + 1);\
            (AF)[4 * kk + 0] = *reinterpret_cast<const uint32_t*>(               \
                cbb + (size_t)i00 * 16 + cc * 4);                                \
            (AF)[4 * kk + 1] = *reinterpret_cast<const uint32_t*>(               \
                cbb + (size_t)i10 * 16 + cc * 4);                                \
            (AF)[4 * kk + 2] = *reinterpret_cast<const uint32_t*>(               \
                cbb + (size_t)i01 * 16 + cc * 4);                                \
            (AF)[4 * kk + 3] = *reinterpret_cast<const uint32_t*>(               \
                cbb + (size_t)i11 * 16 + cc * 4);                                \
        }                                                                        \
    }

    // ---- prologue ----
    int4 sidx0 = __ldg(qp4);          // idx for it=0
    int4 sidx1 = __ldg(qp4 + 2);      // idx for it=1
    uint4 bv = *reinterpret_cast<const uint4*>(xh + (size_t)r0 * IN_F + kbase + j * 8);

    uint32_t af[16];
    GATHER_FRAGS(af, sidx0);

    for (int it = 0; it < NIT; ++it) {
        const int s = it & 1;

        // store this iter's B tile
        uint32_t boff = (uint32_t)((r0 << 7) | (j << 4));
        *reinterpret_cast<uint4*>(sm + s * 4096 + SWZ(boff)) = bv;
        __syncthreads();

        // ---- prefetch next iter (A frags + B + idx), latency hidden by MMAs ----
        const bool more = (it + 1 < NIT);
        uint32_t afN[16];
        int4 sidxN;
        uint4 bvn;
        if (more) {
            bvn = *reinterpret_cast<const uint4*>(
                xh + (size_t)r0 * IN_F + kbase + (it + 1) * 64 + j * 8);
            GATHER_FRAGS(afN, sidx1);
            if (it + 2 < NIT) sidxN = __ldg(qp4 + (it + 2) * 2);
        }

        // ---- MMAs on buffer s ----
        const uint32_t Bb = sb + (uint32_t)s * 4096;
        #pragma unroll
        for (int kk = 0; kk < 4; ++kk) {
            uint32_t b00, b01, b10, b11, b20, b21, b30, b31;
            uint32_t off0 = b_base + (uint32_t)(kk * 32);
            ldmat_x4(Bb + SWZ(off0), b00, b01, b10, b11);
            uint32_t off1 = off0 + (16u << 7);   // tokens +16
            ldmat_x4(Bb + SWZ(off1), b20, b21, b30, b31);
            mma16816(c[0], af[4*kk], af[4*kk+1], af[4*kk+2], af[4*kk+3], b00, b01);
            mma16816(c[1], af[4*kk], af[4*kk+1], af[4*kk+2], af[4*kk+3], b10, b11);
            mma16816(c[2], af[4*kk], af[4*kk+1], af[4*kk+2], af[4*kk+3], b20, b21);
            mma16816(c[3], af[4*kk], af[4*kk+1], af[4*kk+2], af[4*kk+3], b30, b31);
        }

        if (more) {
            #pragma unroll
            for (int i = 0; i < 16; ++i) af[i] = afN[i];
            sidx1 = sidxN;
            bv = bvn;
        }
    }
#undef GATHER_FRAGS

    // ---- epilogue: atomic-accumulate into g_z ----
    const int row0 = m0 + wid * 16 + (lid >> 2);
    const int col0 = (lid & 3) * 2;
    #pragma unroll
    for (int g = 0; g < 4; ++g) {
        int t0 = g * 8 + col0;
        atomicAdd(&g_z[(size_t)(t0    ) * OUT_F + row0    ], c[g][0]);
        atomicAdd(&g_z[(size_t)(t0 + 1) * OUT_F + row0    ], c[g][1]);
        atomicAdd(&g_z[(size_t)(t0    ) * OUT_F + row0 + 8], c[g][2]);
        atomicAdd(&g_z[(size_t)(t0 + 1) * OUT_F + row0 + 8], c[g][3]);
    }
}

// ---------------- K_out1: FWHT stage 1 (H_1024) of g_z ----------------
__global__ void __launch_bounds__(256) k_out1() {
    __shared__ float s[1024];
    int t = blockIdx.x >> 3;          // token
    int ch = blockIdx.x & 7;          // chunk
    size_t base = (size_t)t * OUT_F + ch * 1024;
    int tid = threadIdx.x;
    reinterpret_cast<float4*>(s)[tid] =
        reinterpret_cast<const float4*>(g_z + base)[tid];
    fwht1024(s, tid);
    #pragma unroll
    for (int pp = 0; pp < 4; ++pp) {
        int i = tid + pp * 256;
        g_tmp[base + i] = s[i];
    }
}

// ---------------- K_out2: FWHT stage 2 (H_8) * SV * Wscale -> out ----------------
__global__ void __launch_bounds__(256) k_out2(const float* __restrict__ SV,
                                              const float* __restrict__ Wscale,
                                              float* __restrict__ out) {
    int gid = blockIdx.x * 256 + threadIdx.x;   // 0..32767
    int t = gid >> 10;
    int i = gid & 1023;
    size_t base = (size_t)t * OUT_F + i;
    float v[8];
    #pragma unroll
    for (int c = 0; c < 8; ++c) v[c] = g_tmp[base + c * 1024];
    fwht8(v);
    const float ws = Wscale[0] * 0.011048543456039806f;   // Wscale / sqrt(8192)
    #pragma unroll
    for (int c = 0; c < 8; ++c)
        out[base + c * 1024] = v[c] * ws * SV[i + c * 1024];
}

// ---------------- launch ----------------
extern "C" void kernel_launch(void* const* d_in, const int* in_sizes, int n_in,
                              void* d_out, int out_size) {
    const float* x      = (const float*)d_in[0];
    const float* cb     = (const float*)d_in[1];
    const int*   qidx   = (const int*)  d_in[2];
    const float* SU     = (const float*)d_in[3];
    const float* SV     = (const float*)d_in[4];
    const float* Wscale = (const float*)d_in[5];
    float* out = (float*)d_out;

    k_pre<<<576, 256>>>(cb, x, SU);
    k_xh2<<<NTOK * 1024 / 256, 256>>>();
    k_main<<<dim3(OUT_F / 128, KSPLIT), 256>>>(qidx);
    k_out1<<<NTOK * NCHUNK, 256>>>();
    k_out2<<<NTOK * 1024 / 256, 256>>>(SV, Wscale, out);
}